// round 8
// baseline (speedup 1.0000x reference)
#include <cuda_runtime.h>
#include <cuda_bf16.h>

#define D       128
#define MAXN    100000
#define MAXE    1600000

typedef unsigned long long u64;

// ---------------------------------------------------------------------------
// Scratch — static __device__ arrays, referenced ONLY inside kernels.
// (NEVER pass these as kernel args: host shadow symbol + GB300 ATS = silent
//  NVLink-C2C traffic at 200GB/s — the round-2/4 5ms regression.)
// ---------------------------------------------------------------------------
__device__ int   g_deg[MAXN];
__device__ float g_scale[MAXN];                    // rsqrt(deg+1)
__device__ float g_inv[MAXN];                      // 1/max(deg,1)
__device__ int   g_rowstart[MAXN];
__device__ int   g_cursor[MAXN];
__device__ int   g_csr[MAXE];                      // src ids grouped by dst
__device__ int   g_total;                          // rowstart allocator
__device__ float g_pre[(size_t)MAXN * D];          // scale*(feat @ W)  (51.2MB)

// ---------------------------------------------------------------------------
// 0) In-degree histogram (g_deg zeroed by previous replay's agg tail)
// ---------------------------------------------------------------------------
__global__ void deg_kernel(const int* __restrict__ dst, int E) {
    int i = blockIdx.x * blockDim.x + threadIdx.x;
    if (i < E) atomicAdd(&g_deg[dst[i]], 1);
}

// ---------------------------------------------------------------------------
// 1) mini-prep: N threads. scale, inv, rowstart, cursor.
// ---------------------------------------------------------------------------
__global__ void prep_kernel(int N) {
    int i = blockIdx.x * blockDim.x + threadIdx.x;
    if (i >= N) return;
    int dg = g_deg[i];
    g_scale[i] = rsqrtf((float)dg + 1.0f);
    g_inv[i]   = 1.0f / (float)(dg > 0 ? dg : 1);
    int rs = atomicAdd(&g_total, dg);
    g_rowstart[i] = rs;
    g_cursor[i]   = rs;
}

// ---------------------------------------------------------------------------
// 2) CSR fill: bucket src by dst
// ---------------------------------------------------------------------------
__global__ void fill_kernel(const int* __restrict__ src,
                            const int* __restrict__ dst, int E) {
    int i = blockIdx.x * blockDim.x + threadIdx.x;
    if (i < E) {
        int p = atomicAdd(&g_cursor[dst[i]], 1);
        g_csr[p] = src[i];
    }
}

// ---------------------------------------------------------------------------
// 3) GEMM: g_pre[n,128] = scale[n] * (feature[n,:] @ W[128,128])
//    cp.async double-buffered, FFMA2 (fma.rn.f32x2) inner loop,
//    scale applied in epilogue (commutes with the row GEMM).
// ---------------------------------------------------------------------------
#define BM 128
#define BN 128
#define BK 16
#define TM 8
#define TN 8
#define AKP 20                  // A row pitch (floats): 16 + 4, keeps 16B align

__device__ __forceinline__ u64 pack2(float lo, float hi) {
    u64 r;
    asm("mov.b64 %0, {%1,%2};" : "=l"(r) : "f"(lo), "f"(hi));
    return r;
}
__device__ __forceinline__ float2 unpack2(u64 v) {
    float2 r;
    asm("mov.b64 {%0,%1}, %2;" : "=f"(r.x), "=f"(r.y) : "l"(v));
    return r;
}
__device__ __forceinline__ void fma2(u64& c, u64 a, u64 b) {
    asm("fma.rn.f32x2 %0, %1, %2, %3;" : "=l"(c) : "l"(a), "l"(b), "l"(c));
}
__device__ __forceinline__ void cp16(unsigned dst, const void* src, int srcbytes) {
    asm volatile("cp.async.cg.shared.global [%0], [%1], 16, %2;"
                 :: "r"(dst), "l"(src), "r"(srcbytes));
}
__device__ __forceinline__ void cp_commit() {
    asm volatile("cp.async.commit_group;");
}
__device__ __forceinline__ void cp_wait0() {
    asm volatile("cp.async.wait_group 0;" ::: "memory");
}

__global__ __launch_bounds__(256)
void gemm_kernel(const float* __restrict__ feat,
                 const float* __restrict__ W,
                 int n) {
    // A: row-major [buf][row][AKP] ; W: k-major [buf][k][BN]
    __shared__ __align__(16) float As[2][BM][AKP];   // 2*128*20*4 = 20.5KB
    __shared__ __align__(16) float Ws[2][BK][BN];    // 2*16*128*4 = 16.4KB

    int block_row = blockIdx.x * BM;
    int tid = threadIdx.x;
    int tx = tid & 15;
    int ty = tid >> 4;

    unsigned as_base = (unsigned)__cvta_generic_to_shared(&As[0][0][0]);
    unsigned ws_base = (unsigned)__cvta_generic_to_shared(&Ws[0][0][0]);

    // Per-thread load slots (2 each for A and W, 512 float4 per tile)
    int a_row0 = (tid)        >> 2;          // 0..63
    int a_row1 = (tid + 256)  >> 2;          // 64..127
    int a_k4   = (tid & 3) * 4;              // 0,4,8,12
    int w_k0   = (tid)       >> 5;           // 0..7
    int w_k1   = (tid + 256) >> 5;           // 8..15
    int w_c4   = (tid & 31) * 4;             // 0..124

    int grow0 = block_row + a_row0;
    int grow1 = block_row + a_row1;
    const float* asrc0 = feat + (size_t)min(grow0, n - 1) * D + a_k4;
    const float* asrc1 = feat + (size_t)min(grow1, n - 1) * D + a_k4;
    int ab0 = (grow0 < n) ? 16 : 0;
    int ab1 = (grow1 < n) ? 16 : 0;

#define ISSUE_TILE(k0, b)                                                      \
    do {                                                                       \
        cp16(as_base + (((b) * BM + a_row0) * AKP + a_k4) * 4, asrc0 + (k0), ab0); \
        cp16(as_base + (((b) * BM + a_row1) * AKP + a_k4) * 4, asrc1 + (k0), ab1); \
        cp16(ws_base + (((b) * BK + w_k0) * BN + w_c4) * 4,                    \
             W + (size_t)((k0) + w_k0) * D + w_c4, 16);                        \
        cp16(ws_base + (((b) * BK + w_k1) * BN + w_c4) * 4,                    \
             W + (size_t)((k0) + w_k1) * D + w_c4, 16);                        \
        cp_commit();                                                           \
    } while (0)

    u64 c2[TM][TN / 2];
#pragma unroll
    for (int i = 0; i < TM; i++)
#pragma unroll
        for (int j = 0; j < TN / 2; j++) c2[i][j] = 0ULL;

    // Prologue: tile 0 into buffer 0
    ISSUE_TILE(0, 0);

    const int NT = D / BK;                   // 8 tiles
#pragma unroll 1
    for (int t = 0; t < NT; t++) {
        cp_wait0();              // tile t landed (for this thread)
        __syncthreads();         // visible to all; also: all warps done computing
                                 // buf[(t+1)&1] from iteration t-1

        if (t < NT - 1) ISSUE_TILE((t + 1) * BK, (t + 1) & 1);

        const float (*Asb)[AKP] = As[t & 1];
        const float (*Wsb)[BN]  = Ws[t & 1];

#pragma unroll
        for (int k = 0; k < BK; k++) {
            float a[TM];
            u64 wv[TN / 2];
#pragma unroll
            for (int i = 0; i < TM; i++) a[i] = Asb[ty * TM + i][k];
            const u64* wp = (const u64*)&Wsb[k][tx * TN];
#pragma unroll
            for (int j = 0; j < TN / 2; j++) wv[j] = wp[j];
#pragma unroll
            for (int i = 0; i < TM; i++) {
                u64 ap = pack2(a[i], a[i]);
#pragma unroll
                for (int j = 0; j < TN / 2; j++)
                    fma2(c2[i][j], ap, wv[j]);
            }
        }
    }

    // Epilogue: apply per-row scale, store
#pragma unroll
    for (int i = 0; i < TM; i++) {
        int row = block_row + ty * TM + i;
        if (row < n) {
            float sc = g_scale[row];
            float2 p0 = unpack2(c2[i][0]);
            float2 p1 = unpack2(c2[i][1]);
            float2 p2 = unpack2(c2[i][2]);
            float2 p3 = unpack2(c2[i][3]);
            int col = tx * TN;
            *(float4*)&g_pre[(size_t)row * D + col] =
                make_float4(p0.x * sc, p0.y * sc, p1.x * sc, p1.y * sc);
            *(float4*)&g_pre[(size_t)row * D + col + 4] =
                make_float4(p2.x * sc, p2.y * sc, p3.x * sc, p3.y * sc);
        }
    }
#undef ISSUE_TILE
}

// ---------------------------------------------------------------------------
// 4) Aggregation (pure gather): one warp per dst node.
//    out[d,:] = inv[d] * sum_{s in nbr(d)} g_pre[s,:] + bias
//    Tail: zero g_deg / g_total for the next graph replay.
// ---------------------------------------------------------------------------
__global__ __launch_bounds__(256)
void agg_kernel(const float* __restrict__ bias,
                float* __restrict__ out,
                int N) {
    int t = blockIdx.x * blockDim.x + threadIdx.x;
    int node = t >> 5;
    int lane = t & 31;
    if (node >= N) return;

    int start = g_rowstart[node];
    int deg   = g_deg[node];
    int end   = start + deg;

    const float4* pre4 = (const float4*)g_pre;

    float4 acc = make_float4(0.f, 0.f, 0.f, 0.f);

    int j = start;
    for (; j + 3 < end; j += 4) {
        int s0 = __ldg(&g_csr[j + 0]);
        int s1 = __ldg(&g_csr[j + 1]);
        int s2 = __ldg(&g_csr[j + 2]);
        int s3 = __ldg(&g_csr[j + 3]);
        float4 v0 = __ldg(pre4 + (size_t)s0 * 32 + lane);
        float4 v1 = __ldg(pre4 + (size_t)s1 * 32 + lane);
        float4 v2 = __ldg(pre4 + (size_t)s2 * 32 + lane);
        float4 v3 = __ldg(pre4 + (size_t)s3 * 32 + lane);
        acc.x += v0.x + v1.x + v2.x + v3.x;
        acc.y += v0.y + v1.y + v2.y + v3.y;
        acc.z += v0.z + v1.z + v2.z + v3.z;
        acc.w += v0.w + v1.w + v2.w + v3.w;
    }
    for (; j < end; j++) {
        int s = __ldg(&g_csr[j]);
        float4 v = __ldg(pre4 + (size_t)s * 32 + lane);
        acc.x += v.x; acc.y += v.y; acc.z += v.z; acc.w += v.w;
    }

    float iv = g_inv[node];
    float4 bb = __ldg((const float4*)bias + lane);
    float4 r;
    r.x = acc.x * iv + bb.x;
    r.y = acc.y * iv + bb.y;
    r.z = acc.z * iv + bb.z;
    r.w = acc.w * iv + bb.w;
    *((float4*)(out + (size_t)node * D) + lane) = r;

    // Reset per-replay state (node-private: this warp already consumed deg)
    if (lane == 0) g_deg[node] = 0;
    if (t == 0)    g_total = 0;
}

// ---------------------------------------------------------------------------
extern "C" void kernel_launch(void* const* d_in, const int* in_sizes, int n_in,
                              void* d_out, int out_size) {
    const float* feature = (const float*)d_in[0];
    const float* W       = (const float*)d_in[1];
    const float* bias    = (const float*)d_in[2];
    const int*   src     = (const int*)d_in[3];
    const int*   dst     = (const int*)d_in[4];
    float*       out     = (float*)d_out;

    int N = in_sizes[0] / D;
    int E = in_sizes[3];

    deg_kernel<<<(E + 255) / 256, 256>>>(dst, E);
    prep_kernel<<<(N + 255) / 256, 256>>>(N);
    fill_kernel<<<(E + 255) / 256, 256>>>(src, dst, E);
    gemm_kernel<<<(N + BM - 1) / BM, 256>>>(feature, W, N);
    {
        long long total = (long long)N * 32;
        agg_kernel<<<(int)((total + 255) / 256), 256>>>(bias, out, N);
    }
}